// round 16
// baseline (speedup 1.0000x reference)
#include <cuda_runtime.h>
#include <cuda_fp16.h>
#include <cstdint>

#define BB   128
#define TT   256
#define NH   1024
#define NI   1024
#define NT   256
#define GRID 128
#define SMEM_DYN 196608

// ---------------- device scratch ----------------
__device__ __align__(128) unsigned char g_sw[7][2][16][8192];   // states 0..5, h=6 (fp16 swizzled)
__device__ __align__(128) unsigned char g_xw[TT][2][16][8192];  // x swizzled (zgemm input)
__device__ __align__(128) unsigned char g_w0w[64][32*4096];     // W0 job blocks (subtiles 0-15 = x-part, 16-31 = h-part)
__device__ __align__(128) unsigned char g_wsw[8][64][16*4096];  // gene job blocks
__device__ __align__(16) float g_s[8][BB*NH];                   // fp32 states s0..s7
__device__ __align__(16) float g_hbuf[BB*NH];
__device__ __align__(16) float g_z[TT][BB][2048];               // precomputed x@W0x (fp32)
__device__ unsigned g_arr[2], g_epo[2];

// ---------------- primitives ----------------
__device__ __forceinline__ void mma16816(float c[4], const uint32_t a[4],
                                         uint32_t b0, uint32_t b1){
  asm volatile(
    "mma.sync.aligned.m16n8k16.row.col.f32.f16.f16.f32 "
    "{%0,%1,%2,%3},{%4,%5,%6,%7},{%8,%9},{%0,%1,%2,%3};\n"
    : "+f"(c[0]), "+f"(c[1]), "+f"(c[2]), "+f"(c[3])
    : "r"(a[0]), "r"(a[1]), "r"(a[2]), "r"(a[3]), "r"(b0), "r"(b1));
}

__device__ __forceinline__ void ldsm4(uint32_t r[4], uint32_t addr){
  asm volatile("ldmatrix.sync.aligned.m8n8.x4.shared.b16 {%0,%1,%2,%3}, [%4];"
    : "=r"(r[0]), "=r"(r[1]), "=r"(r[2]), "=r"(r[3]) : "r"(addr));
}

__device__ __forceinline__ void bulkcp(uint32_t dst, const void* src, uint32_t bytes, uint32_t mbar){
  asm volatile(
    "cp.async.bulk.shared::cta.global.mbarrier::complete_tx::bytes [%0], [%1], %2, [%3];"
    :: "r"(dst), "l"(src), "r"(bytes), "r"(mbar) : "memory");
}

__device__ __forceinline__ void expect_tx(uint32_t mbar, uint32_t bytes){
  asm volatile("mbarrier.arrive.expect_tx.shared.b64 _, [%0], %1;"
    :: "r"(mbar), "r"(bytes) : "memory");
}

__device__ __forceinline__ void mbar_wait(uint32_t mbar, int phase){
  uint32_t done;
  asm volatile(
    "{\n\t.reg .pred p;\n\t"
    "mbarrier.try_wait.parity.acquire.cta.shared::cta.b64 p, [%1], %2;\n\t"
    "selp.b32 %0, 1, 0, p;\n\t}"
    : "=r"(done) : "r"(mbar), "r"((uint32_t)phase) : "memory");
  if (!done){
    asm volatile(
      "{\n\t.reg .pred P1;\n\t"
      "WAIT_LOOP_%=:\n\t"
      "mbarrier.try_wait.parity.acquire.cta.shared::cta.b64 P1, [%0], %1, 0x989680;\n\t"
      "@P1 bra.uni WAIT_DONE_%=;\n\t"
      "bra.uni WAIT_LOOP_%=;\n\t"
      "WAIT_DONE_%=:\n\t}"
      :: "r"(mbar), "r"((uint32_t)phase) : "memory");
  }
}

__device__ __forceinline__ void gsync(unsigned &target, int grp, unsigned grpSize){
  __syncthreads();
  if (threadIdx.x == 0){
    target += grpSize;
    unsigned old;
    asm volatile("atom.add.release.gpu.global.u32 %0, [%1], %2;"
                 : "=r"(old) : "l"(&g_arr[grp]), "r"(1u) : "memory");
    if (old + 1 == target){
      asm volatile("st.release.gpu.global.u32 [%0], %1;" :: "l"(&g_epo[grp]), "r"(target) : "memory");
    } else {
      unsigned e; int spins = 0;
      do {
        asm volatile("ld.acquire.gpu.global.u32 %0, [%1];" : "=r"(e) : "l"(&g_epo[grp]) : "memory");
        if (++spins > 32) __nanosleep(64);
      } while ((int)(e - target) < 0);
    }
  }
  __syncthreads();
}

__device__ __forceinline__ float act_fn(int act, float v){
  switch (act){
    case 0:  return 1.f/(1.f + __expf(-v));
    case 1:  return fmaxf(v, 0.f);
    case 2:  return v;
    default: return tanhf(v);
  }
}

__device__ __forceinline__ void st_swz(unsigned char* base, int m, int k, __half v){
  unsigned char* p = base + ((size_t)((m>>6)*16 + (k>>6)))*8192;
  uint32_t o = (uint32_t)((m&63)*128 + (k&63)*2);
  o ^= (o>>3)&0x70;
  *(__half*)(p + o) = v;
}

// ---------------- GEMM job (all phases K=1024, NC=4) ----------------
// MODE 0: single gene (4-stage, 48KB/stage; optional Z add for G0).
// MODE 1: G2 — genes 1,2,3 share A=s1 (2-stage, 80KB).
// MODE 2: G4F — genes 5+7 share A=s5; finalize step (3-stage, 64KB).
// MODE 3: G3 — gene4 on A=s2 -> s5, gene6 on A2=s3 -> s7 (2-stage, 96KB).
template<int MODE>
__device__ void job(
    const unsigned char* a1, const unsigned char* a2,
    const unsigned char* w0p, const unsigned char* w1p, const unsigned char* w2p,
    const float* __restrict__ resid, const float* __restrict__ resid2,
    const float* __restrict__ zrow,
    float* __restrict__ outS, unsigned char* swz,
    int m0, int j0t, int act,
    uint32_t sbase, uint32_t mb0, int ph[4], int tid,
    float* __restrict__ out, int t)
{
  constexpr int NWB    = (MODE==1) ? 3 : ((MODE==0) ? 1 : 2);
  constexpr int NSTAGE = (MODE==0) ? 4 : ((MODE==2) ? 3 : 2);
  constexpr uint32_t STRIDE = (MODE==0) ? 49152u :
                              ((MODE==1) ? 81920u : ((MODE==3) ? 98304u : 65536u));
  constexpr uint32_t WOFF = (MODE==3) ? 65536u : 32768u;
  constexpr int NC = 4;
  const uint32_t TX = WOFF + NWB*16384u;

  const int lane = tid & 31, warp = tid >> 5;
  const int wm = warp >> 1, wn = warp & 1;

  float C[2*NWB][4];
  #pragma unroll
  for (int n=0;n<2*NWB;n++)
    #pragma unroll
    for (int q=0;q<4;q++) C[n][q]=0.f;

  const unsigned char* wp[3] = {w0p, w1p, w2p};

  auto load_chunk = [&](int c, int st){
    if (tid == 0){
      uint32_t mbar = mb0 + st*8;
      int ks = c*4;                      // k-subtile index (k0 = c*256)
      uint32_t d = sbase + st*STRIDE;
      bulkcp(d, a1 + (size_t)ks*8192, 32768u, mbar);
      if (MODE == 3)
        bulkcp(d + 32768u, a2 + (size_t)ks*8192, 32768u, mbar);
      #pragma unroll
      for (int w=0; w<NWB; w++)
        bulkcp(d + WOFF + w*16384u, wp[w] + (size_t)ks*4096, 16384u, mbar);
    }
  };

  if (tid == 0){
    #pragma unroll
    for (int s=0; s<NSTAGE; s++) expect_tx(mb0 + s*8, TX);
  }
  __syncthreads();
  #pragma unroll
  for (int s=0; s<NSTAGE; s++) if (s < NC) load_chunk(s, s);

  const uint32_t a_row = (uint32_t)(wm*16 + (lane & 15));
  const uint32_t a_kb  = (uint32_t)((lane >> 4) * 16);
  const int sub2 = lane >> 3;
  const uint32_t b_row = (uint32_t)(wn*16 + ((sub2 >> 1) << 3) + (lane & 7));
  const uint32_t b_kb  = (uint32_t)((sub2 & 1) * 16);
  const uint32_t aXor = (a_row & 7) << 4;
  const uint32_t bXor = (b_row & 7) << 4;
  const uint32_t aOff = a_row * 128;
  const uint32_t bOff = b_row * 128;

  for (int c=0; c<NC; c++){
    const int st = c % NSTAGE;
    const uint32_t mbar = mb0 + st*8;
    mbar_wait(mbar, ph[st]); ph[st] ^= 1;
    if (c + NSTAGE < NC && tid == 0) expect_tx(mbar, TX);

    const uint32_t base = sbase + st*STRIDE;
    #pragma unroll
    for (int sub=0; sub<4; sub++){
      const uint32_t aSub = base + sub*8192 + aOff;
      const uint32_t wSub = base + WOFF + sub*4096 + bOff;
      #pragma unroll
      for (int k16=0; k16<4; k16++){
        const uint32_t ak = (((uint32_t)(k16*32) + a_kb) ^ aXor);
        const uint32_t bk = (((uint32_t)(k16*32) + b_kb) ^ bXor);
        uint32_t A4[4];
        ldsm4(A4, aSub + ak);
        if (MODE == 3){
          uint32_t A8[4], B4[4], B6[4];
          ldsm4(A8, base + 32768 + sub*8192 + aOff + ak);
          ldsm4(B4, wSub + bk);
          ldsm4(B6, wSub + 16384 + bk);
          mma16816(C[0], A4, B4[0], B4[1]);
          mma16816(C[1], A4, B4[2], B4[3]);
          mma16816(C[2], A8, B6[0], B6[1]);
          mma16816(C[3], A8, B6[2], B6[3]);
        } else {
          #pragma unroll
          for (int w=0; w<NWB; w++){
            uint32_t B4[4];
            ldsm4(B4, wSub + w*16384 + bk);
            mma16816(C[2*w+0], A4, B4[0], B4[1]);
            mma16816(C[2*w+1], A4, B4[2], B4[3]);
          }
        }
      }
    }
    __syncthreads();
    if (c + NSTAGE < NC) load_chunk(c+NSTAGE, st);
  }

  // epilogue
  #pragma unroll
  for (int f=0; f<2; f++){
    const int col = j0t*16 + wn*8 + f*4 + (lane & 3);
    #pragma unroll
    for (int hf=0; hf<2; hf++){
      const int m = m0 + wm*16 + (lane>>2) + hf*8;
      const int idx = m*NH + col;
      if (MODE == 0){
        float cv = C[f][hf*2], hv = C[f][hf*2+1];
        if (zrow){
          cv += zrow[(size_t)m*2048 + col];
          hv += zrow[(size_t)m*2048 + 1024 + col];
        }
        float sp = __ldcg(resid + idx);
        float g = 1.f/(1.f + __expf(-cv));
        float v = fmaf(g, act_fn(act, hv) - sp, sp);
        outS[idx] = v;
        if (swz) st_swz(swz, m, col, __float2half_rn(v));
      } else if (MODE == 1){
        float sp = __ldcg(resid + idx);
        #pragma unroll
        for (int w=0; w<3; w++){
          float g = 1.f/(1.f + __expf(-C[2*w+f][hf*2]));
          float v = fmaf(g, act_fn((w==2)?2:1, C[2*w+f][hf*2+1]) - sp, sp);
          g_s[2+w][idx] = v;
          if (w < 2) st_swz(&g_sw[2+w][0][0][0], m, col, __float2half_rn(v));
        }
      } else if (MODE == 3){
        float sp2 = __ldcg(resid + idx);
        float g4 = 1.f/(1.f + __expf(-C[f][hf*2]));
        float v5 = fmaf(g4, tanhf(C[f][hf*2+1]) - sp2, sp2);
        g_s[5][idx] = v5;
        st_swz(&g_sw[5][0][0][0], m, col, __float2half_rn(v5));
        float sp3 = __ldcg(resid2 + idx);
        float g6 = 1.f/(1.f + __expf(-C[2+f][hf*2]));
        float v7 = fmaf(g6, tanhf(C[2+f][hf*2+1]) - sp3, sp3);
        g_s[7][idx] = v7;
      } else {
        float s5v = __ldcg(resid + idx);
        float g5 = 1.f/(1.f + __expf(-C[f][hf*2]));
        float s6 = fmaf(g5, 1.f/(1.f + __expf(-C[f][hf*2+1])) - s5v, s5v);
        float g7 = 1.f/(1.f + __expf(-C[2+f][hf*2]));
        float s8 = fmaf(g7, fmaxf(C[2+f][hf*2+1], 0.f) - s5v, s5v);
        float mv = (__ldcg(&g_s[1][idx]) + __ldcg(&g_s[2][idx]) +
                    __ldcg(&g_s[3][idx]) + __ldcg(&g_s[4][idx]) +
                    s5v + s6 + __ldcg(&g_s[7][idx]) + s8) * 0.125f;
        g_hbuf[idx] = mv;
        st_swz(&g_sw[6][0][0][0], m, col, __float2half_rn(mv));
        out[((size_t)m*TT + t)*NH + col] = mv;
        if (t == TT-1) out[(size_t)BB*TT*NH + idx] = mv;
      }
    }
  }
}

// ---------------- persistent scan kernel ----------------
__global__ void __launch_bounds__(NT,1) rnn_persistent(float* __restrict__ out){
  extern __shared__ __align__(128) unsigned char dsm[];
  __shared__ __align__(8) uint64_t s_mbar[4];

  const int tid = threadIdx.x;
  uint32_t sbase, mb0;
  { uint32_t a; asm("{ .reg .u64 t; cvta.to.shared.u64 t, %1; cvt.u32.u64 %0, t; }" : "=r"(a) : "l"(dsm)); sbase = a; }
  { uint32_t a; asm("{ .reg .u64 t; cvta.to.shared.u64 t, %1; cvt.u32.u64 %0, t; }" : "=r"(a) : "l"(&s_mbar[0])); mb0 = a; }

  if (tid == 0){
    #pragma unroll
    for (int b=0;b<4;b++)
      asm volatile("mbarrier.init.shared.b64 [%0], %1;" :: "r"(mb0+b*8), "r"(1u) : "memory");
  }
  __syncthreads();

  const unsigned grpSize = gridDim.x >> 1;
  const int grp = (blockIdx.x >= (int)grpSize) ? 1 : 0;
  const int lb  = blockIdx.x - grp*(int)grpSize;
  const int half = grp;
  const int m0 = half*64;

  int ph[4] = {0,0,0,0};
  unsigned target = 0;

  for (int t = 0; t < TT; t++){
    // G0: h @ W0h + Z -> s0 (tanh, resid h). K=1024
    for (int j0t = lb; j0t < 64; j0t += grpSize)
      job<0>(&g_sw[6][half][0][0], nullptr,
             g_w0w[j0t] + 16*4096, nullptr, nullptr,
             g_hbuf, nullptr, &g_z[t][0][0],
             g_s[0], &g_sw[0][0][0][0],
             m0, j0t, 3, sbase, mb0, ph, tid, out, t);
    gsync(target, grp, grpSize);

    // G1: gene0 (sigmoid) s0 -> s1
    for (int j0t = lb; j0t < 64; j0t += grpSize)
      job<0>(&g_sw[0][half][0][0], nullptr,
             g_wsw[0][j0t], nullptr, nullptr,
             g_s[0], nullptr, nullptr,
             g_s[1], &g_sw[1][0][0][0],
             m0, j0t, 0, sbase, mb0, ph, tid, out, t);
    gsync(target, grp, grpSize);

    // G2 fused: genes 1,2,3 from s1 -> s2,s3,s4
    for (int j0t = lb; j0t < 64; j0t += grpSize)
      job<1>(&g_sw[1][half][0][0], nullptr,
             g_wsw[1][j0t], g_wsw[2][j0t], g_wsw[3][j0t],
             g_s[1], nullptr, nullptr, nullptr, nullptr,
             m0, j0t, 0, sbase, mb0, ph, tid, out, t);
    gsync(target, grp, grpSize);

    // G3 fused: gene4 (s2->s5) + gene6 (s3->s7), dual-A
    for (int j0t = lb; j0t < 64; j0t += grpSize)
      job<3>(&g_sw[2][half][0][0], &g_sw[3][half][0][0],
             g_wsw[4][j0t], g_wsw[6][j0t], nullptr,
             g_s[2], g_s[3], nullptr, nullptr, nullptr,
             m0, j0t, 3, sbase, mb0, ph, tid, out, t);
    gsync(target, grp, grpSize);

    // G4+F fused: genes 5+7 from s5; finalize h
    for (int j0t = lb; j0t < 64; j0t += grpSize)
      job<2>(&g_sw[5][half][0][0], nullptr,
             g_wsw[5][j0t], g_wsw[7][j0t], nullptr,
             g_s[5], nullptr, nullptr, nullptr, nullptr,
             m0, j0t, 0, sbase, mb0, ph, tid, out, t);
    gsync(target, grp, grpSize);
  }
}

// ---------------- prologue: Z = x @ W0x ----------------
// One CTA per (t, half): x half-block (128KB) resident in smem; loop j0t with
// a 2-stage W ring (32KB chunks). Raw fp32 output to g_z.
__global__ void __launch_bounds__(NT,1) zgemm(){
  extern __shared__ __align__(128) unsigned char dsm[];
  __shared__ __align__(8) uint64_t zb[3];

  const int tid = threadIdx.x;
  uint32_t sbase, mb;
  { uint32_t a; asm("{ .reg .u64 t; cvta.to.shared.u64 t, %1; cvt.u32.u64 %0, t; }" : "=r"(a) : "l"(dsm)); sbase = a; }
  { uint32_t a; asm("{ .reg .u64 t; cvta.to.shared.u64 t, %1; cvt.u32.u64 %0, t; }" : "=r"(a) : "l"(&zb[0])); mb = a; }

  const int t = blockIdx.x >> 1, half = blockIdx.x & 1;
  const int lane = tid & 31, warp = tid >> 5;
  const int wm = warp >> 1, wn = warp & 1;

  if (tid == 0){
    #pragma unroll
    for (int b=0;b<3;b++)
      asm volatile("mbarrier.init.shared.b64 [%0], %1;" :: "r"(mb+b*8), "r"(1u) : "memory");
  }
  __syncthreads();
  if (tid == 0){
    expect_tx(mb+16, 131072u);
    bulkcp(sbase, &g_xw[t][half][0][0], 131072u, mb+16);
    expect_tx(mb,    32768u);
    bulkcp(sbase+131072u,          &g_w0w[0][0],     32768u, mb);
    expect_tx(mb+8,  32768u);
    bulkcp(sbase+131072u+32768u,   &g_w0w[0][32768], 32768u, mb+8);
  }
  __syncthreads();
  mbar_wait(mb+16, 0);

  const uint32_t a_row = (uint32_t)(wm*16 + (lane & 15));
  const uint32_t a_kb  = (uint32_t)((lane >> 4) * 16);
  const int sub2 = lane >> 3;
  const uint32_t b_row = (uint32_t)(wn*16 + ((sub2 >> 1) << 3) + (lane & 7));
  const uint32_t b_kb  = (uint32_t)((sub2 & 1) * 16);
  const uint32_t aXor = (a_row & 7) << 4;
  const uint32_t bXor = (b_row & 7) << 4;
  const uint32_t aOff = a_row * 128;
  const uint32_t bOff = b_row * 128;

  float C[2][4];
  #pragma unroll
  for (int n=0;n<2;n++)
    #pragma unroll
    for (int q=0;q<4;q++) C[n][q]=0.f;

  int ph2[2] = {0,0};
  for (int ch=0; ch<128; ch++){
    const int st = ch & 1;
    const int j = ch >> 1, c = ch & 1;
    mbar_wait(mb + st*8, ph2[st]); ph2[st] ^= 1;

    #pragma unroll
    for (int sub=0; sub<8; sub++){
      const uint32_t aSub = sbase + (c*8 + sub)*8192 + aOff;
      const uint32_t wSub = sbase + 131072u + st*32768u + sub*4096 + bOff;
      #pragma unroll
      for (int k16=0; k16<4; k16++){
        const uint32_t ak = (((uint32_t)(k16*32) + a_kb) ^ aXor);
        const uint32_t bk = (((uint32_t)(k16*32) + b_kb) ^ bXor);
        uint32_t A4[4], B4[4];
        ldsm4(A4, aSub + ak);
        ldsm4(B4, wSub + bk);
        mma16816(C[0], A4, B4[0], B4[1]);
        mma16816(C[1], A4, B4[2], B4[3]);
      }
    }
    __syncthreads();

    if (c == 1){
      #pragma unroll
      for (int f=0; f<2; f++){
        const int col = j*16 + wn*8 + f*4 + (lane & 3);
        #pragma unroll
        for (int hf=0; hf<2; hf++){
          const int m = half*64 + wm*16 + (lane>>2) + hf*8;
          g_z[t][m][col]        = C[f][hf*2];
          g_z[t][m][1024 + col] = C[f][hf*2+1];
        }
      }
      #pragma unroll
      for (int n=0;n<2;n++)
        #pragma unroll
        for (int q=0;q<4;q++) C[n][q]=0.f;
    }

    if (ch + 2 < 128 && tid == 0){
      int j2 = (ch+2) >> 1, c2 = (ch+2) & 1;
      expect_tx(mb + st*8, 32768u);
      bulkcp(sbase + 131072u + st*32768u, &g_w0w[j2][c2*32768], 32768u, mb + st*8);
    }
  }
}

// ---------------- prologue kernels ----------------
__global__ void wswz(const float* __restrict__ in, unsigned char* __restrict__ outp, int K){
  __shared__ float tile[32][65];
  const float* src = in + (size_t)blockIdx.z*K*2048;
  unsigned char* dst = outp + (((size_t)blockIdx.z*64 + blockIdx.x)*(K/64) + blockIdx.y)*4096;
  int j0 = blockIdx.x*16, k0 = blockIdx.y*64;
  int tx = threadIdx.x, ty = threadIdx.y;
  int w = tx;
  int col = (j0 + (w>>1)) + (w&1)*1024;
  for (int r=0;r<8;r++){
    int k = ty + r*8;
    tile[w][k] = src[(size_t)(k0+k)*2048 + col];
  }
  __syncthreads();
  for (int q=0;q<4;q++){
    int ww = ty + q*8;
    __half2 v = __floats2half2_rn(tile[ww][tx*2], tile[ww][tx*2+1]);
    uint32_t o = (uint32_t)(ww*128 + tx*4);
    o ^= (o>>3)&0x70;
    *(__half2*)(dst + o) = v;
  }
}

__global__ void xswz(const float* __restrict__ x, unsigned char* __restrict__ xs){
  int t = blockIdx.x;
  int half = blockIdx.y >> 4, st = blockIdx.y & 15;
  unsigned char* dst = xs + (((size_t)t*2 + half)*16 + st)*8192;
  int tid = threadIdx.x;
  int row = tid >> 2, kq = (tid & 3)*16;
  const float* src = x + ((size_t)(half*64 + row)*TT + t)*NI + st*64 + kq;
  #pragma unroll
  for (int i=0;i<2;i++){
    float4 a = *(const float4*)(src + i*8);
    float4 b = *(const float4*)(src + i*8 + 4);
    __half2 h0 = __floats2half2_rn(a.x,a.y), h1 = __floats2half2_rn(a.z,a.w);
    __half2 h2 = __floats2half2_rn(b.x,b.y), h3 = __floats2half2_rn(b.z,b.w);
    uint32_t o = (uint32_t)(row*128 + (kq + i*8)*2);
    o ^= (o>>3)&0x70;
    *(uint4*)(dst + o) = make_uint4(*(uint32_t*)&h0, *(uint32_t*)&h1,
                                    *(uint32_t*)&h2, *(uint32_t*)&h3);
  }
}

__global__ void hswz(const float* __restrict__ h0){
  int tid = blockIdx.x*blockDim.x + threadIdx.x;
  int m = tid >> 10, k = tid & 1023;
  float v = h0[tid];
  g_hbuf[tid] = v;
  st_swz(&g_sw[6][0][0][0], m, k, __float2half_rn(v));
}

__global__ void reset_kernel(){
  g_arr[0] = 0; g_arr[1] = 0; g_epo[0] = 0; g_epo[1] = 0;
}

// ---------------- host launch ----------------
extern "C" void kernel_launch(void* const* d_in, const int* in_sizes, int n_in,
                              void* d_out, int out_size){
  const float *x=nullptr, *h0=nullptr, *W0=nullptr, *Ws=nullptr;
  for (int i=0;i<n_in;i++){
    long n = in_sizes[i];
    if      (n == (long)BB*TT*NI)   x  = (const float*)d_in[i];
    else if (n == (long)BB*NH)      h0 = (const float*)d_in[i];
    else if (n == (long)2048*2048)  W0 = (const float*)d_in[i];
    else if (n == (long)8*NH*2048)  Ws = (const float*)d_in[i];
  }
  if (!x || !h0 || !W0 || !Ws) return;
  float* out = (float*)d_out;

  void* p;
  cudaGetSymbolAddress(&p, g_xw);  unsigned char* xw_p = (unsigned char*)p;
  cudaGetSymbolAddress(&p, g_w0w); unsigned char* w0_p = (unsigned char*)p;
  cudaGetSymbolAddress(&p, g_wsw); unsigned char* ws_p = (unsigned char*)p;

  cudaFuncSetAttribute(rnn_persistent, cudaFuncAttributeMaxDynamicSharedMemorySize, SMEM_DYN);
  cudaFuncSetAttribute(zgemm,          cudaFuncAttributeMaxDynamicSharedMemorySize, SMEM_DYN);

  int dev = 0, nsm = 0;
  cudaGetDevice(&dev);
  cudaDeviceGetAttribute(&nsm, cudaDevAttrMultiProcessorCount, dev);
  int grid = (nsm < GRID) ? (nsm & ~1) : GRID;

  wswz<<<dim3(64,32,1), dim3(32,8)>>>(W0, w0_p, 2048);
  wswz<<<dim3(64,16,8), dim3(32,8)>>>(Ws, ws_p, 1024);
  xswz<<<dim3(TT,32), 256>>>(x, xw_p);
  hswz<<<512,256>>>(h0);
  reset_kernel<<<1,1>>>();
  zgemm<<<TT*2, NT, SMEM_DYN>>>();

  rnn_persistent<<<grid, NT, SMEM_DYN>>>(out);
  (void)out_size;
}

// round 17
// speedup vs baseline: 1.0280x; 1.0280x over previous
#include <cuda_runtime.h>
#include <cuda_fp16.h>
#include <cstdint>

#define BB   128
#define TT   256
#define NH   1024
#define NI   1024
#define NT   256
#define GRID 128
#define SMEM_DYN 196608   // 192KB: 4x48KB (MODE0), 2x80KB (MODE1), 2x96KB (MODE3), 3x64KB (MODE2)

// ---------------- device scratch (swizzled tile layouts) ----------------
__device__ __align__(128) unsigned char g_sw[7][2][16][8192];   // states 0..5, h=6
__device__ __align__(128) unsigned char g_xw[TT][2][16][8192];  // x per timestep
__device__ __align__(128) unsigned char g_w0w[64][32*4096];     // W0 job blocks
__device__ __align__(128) unsigned char g_wsw[8][64][16*4096];  // gene job blocks
__device__ __align__(16) float g_s[8][BB*NH];                   // fp32 states s0..s7
__device__ __align__(16) float g_hbuf[BB*NH];
// per-half barrier counters, 256B apart (no false sharing between halves or arr/epo)
__device__ __align__(256) unsigned g_arr[2][64];
__device__ __align__(256) unsigned g_epo[2][64];

// ---------------- primitives ----------------
__device__ __forceinline__ void mma16816(float c[4], const uint32_t a[4],
                                         uint32_t b0, uint32_t b1){
  asm volatile(
    "mma.sync.aligned.m16n8k16.row.col.f32.f16.f16.f32 "
    "{%0,%1,%2,%3},{%4,%5,%6,%7},{%8,%9},{%0,%1,%2,%3};\n"
    : "+f"(c[0]), "+f"(c[1]), "+f"(c[2]), "+f"(c[3])
    : "r"(a[0]), "r"(a[1]), "r"(a[2]), "r"(a[3]), "r"(b0), "r"(b1));
}

__device__ __forceinline__ void ldsm4(uint32_t r[4], uint32_t addr){
  asm volatile("ldmatrix.sync.aligned.m8n8.x4.shared.b16 {%0,%1,%2,%3}, [%4];"
    : "=r"(r[0]), "=r"(r[1]), "=r"(r[2]), "=r"(r[3]) : "r"(addr));
}

__device__ __forceinline__ void bulkcp(uint32_t dst, const void* src, uint32_t bytes, uint32_t mbar){
  asm volatile(
    "cp.async.bulk.shared::cta.global.mbarrier::complete_tx::bytes [%0], [%1], %2, [%3];"
    :: "r"(dst), "l"(src), "r"(bytes), "r"(mbar) : "memory");
}

__device__ __forceinline__ void expect_tx(uint32_t mbar, uint32_t bytes){
  asm volatile("mbarrier.arrive.expect_tx.shared.b64 _, [%0], %1;"
    :: "r"(mbar), "r"(bytes) : "memory");
}

__device__ __forceinline__ void mbar_wait(uint32_t mbar, int phase){
  uint32_t done;
  asm volatile(
    "{\n\t.reg .pred p;\n\t"
    "mbarrier.try_wait.parity.acquire.cta.shared::cta.b64 p, [%1], %2;\n\t"
    "selp.b32 %0, 1, 0, p;\n\t}"
    : "=r"(done) : "r"(mbar), "r"((uint32_t)phase) : "memory");
  if (!done){
    asm volatile(
      "{\n\t.reg .pred P1;\n\t"
      "WAIT_LOOP_%=:\n\t"
      "mbarrier.try_wait.parity.acquire.cta.shared::cta.b64 P1, [%0], %1, 0x989680;\n\t"
      "@P1 bra.uni WAIT_DONE_%=;\n\t"
      "bra.uni WAIT_LOOP_%=;\n\t"
      "WAIT_DONE_%=:\n\t}"
      :: "r"(mbar), "r"((uint32_t)phase) : "memory");
  }
}

// per-half-group barrier (padded counters)
__device__ __forceinline__ void gsync(unsigned &target, int grp, unsigned grpSize){
  __syncthreads();
  if (threadIdx.x == 0){
    target += grpSize;
    unsigned old;
    asm volatile("atom.add.release.gpu.global.u32 %0, [%1], %2;"
                 : "=r"(old) : "l"(&g_arr[grp][0]), "r"(1u) : "memory");
    if (old + 1 == target){
      asm volatile("st.release.gpu.global.u32 [%0], %1;" :: "l"(&g_epo[grp][0]), "r"(target) : "memory");
    } else {
      unsigned e; int spins = 0;
      do {
        asm volatile("ld.acquire.gpu.global.u32 %0, [%1];" : "=r"(e) : "l"(&g_epo[grp][0]) : "memory");
        if (++spins > 32) __nanosleep(64);
      } while ((int)(e - target) < 0);
    }
  }
  __syncthreads();
}

__device__ __forceinline__ float act_fn(int act, float v){
  switch (act){
    case 0:  return 1.f/(1.f + __expf(-v));
    case 1:  return fmaxf(v, 0.f);
    case 2:  return v;
    default: return tanhf(v);
  }
}

// write fp16 value into swizzled state layout: base points at [2][16][8192] block
__device__ __forceinline__ void st_swz(unsigned char* base, int m, int k, __half v){
  unsigned char* p = base + ((size_t)((m>>6)*16 + (k>>6)))*8192;
  uint32_t o = (uint32_t)((m&63)*128 + (k&63)*2);
  o ^= (o>>3)&0x70;
  *(__half*)(p + o) = v;
}

// ---------------- GEMM job ----------------
// MODE 0: single gene (4-stage, 48KB stride) — G0 (NC=8, A switches x->h), G1 (NC=4).
// MODE 1: G2 — genes 1,2,3 share A=s1 (2-stage, 80KB).
// MODE 2: G4F — genes 5+7 share A=s5; finalize step (3-stage, 64KB).
// MODE 3: G3 — gene4 on A=s2 -> s5, gene6 on A2=s3 -> s7 (2-stage, 96KB).
template<int MODE, bool G0MODE>
__device__ void job(
    const unsigned char* a1, const unsigned char* a2,
    const unsigned char* w0p, const unsigned char* w1p, const unsigned char* w2p,
    const float* __restrict__ resid, const float* __restrict__ resid2,
    float* __restrict__ outS, unsigned char* swz,
    int m0, int j0t, int act, int NC,
    uint32_t sbase, uint32_t mb0, int ph[4], int tid,
    float* __restrict__ out, int t)
{
  constexpr int NWB    = (MODE==1) ? 3 : ((MODE==0) ? 1 : 2);
  constexpr int NSTAGE = (MODE==0) ? 4 : ((MODE==2) ? 3 : 2);
  constexpr uint32_t STRIDE = (MODE==0) ? 49152u :
                              ((MODE==1) ? 81920u : ((MODE==3) ? 98304u : 65536u));
  constexpr uint32_t WOFF   = (MODE==3) ? 65536u : 32768u;
  const uint32_t TX = WOFF + NWB*16384u;

  const int lane = tid & 31, warp = tid >> 5;
  const int wm = warp >> 1, wn = warp & 1;

  float C[2*NWB][4];
  #pragma unroll
  for (int n=0;n<2*NWB;n++)
    #pragma unroll
    for (int q=0;q<4;q++) C[n][q]=0.f;

  const unsigned char* wp[3] = {w0p, w1p, w2p};

  auto load_chunk = [&](int c, int st){
    if (tid == 0){
      uint32_t mbar = mb0 + st*8;
      int k0 = c*256;
      uint32_t d = sbase + st*STRIDE;
      const unsigned char* as = (G0MODE && k0 >= 1024)
          ? (a2 + ((size_t)((k0-1024)>>6))*8192)
          : (a1 + ((size_t)(k0>>6))*8192);
      bulkcp(d, as, 32768u, mbar);
      if (MODE == 3)
        bulkcp(d + 32768u, a2 + ((size_t)(k0>>6))*8192, 32768u, mbar);
      #pragma unroll
      for (int w=0; w<NWB; w++)
        bulkcp(d + WOFF + w*16384u, wp[w] + ((size_t)(k0>>6))*4096, 16384u, mbar);
    }
  };

  if (tid == 0){
    #pragma unroll
    for (int s=0; s<NSTAGE; s++) expect_tx(mb0 + s*8, TX);
  }
  __syncthreads();
  #pragma unroll
  for (int s=0; s<NSTAGE; s++) if (s < NC) load_chunk(s, s);

  const uint32_t a_row = (uint32_t)(wm*16 + (lane & 15));
  const uint32_t a_kb  = (uint32_t)((lane >> 4) * 16);
  const int sub2 = lane >> 3;
  const uint32_t b_row = (uint32_t)(wn*16 + ((sub2 >> 1) << 3) + (lane & 7));
  const uint32_t b_kb  = (uint32_t)((sub2 & 1) * 16);
  const uint32_t aXor = (a_row & 7) << 4;
  const uint32_t bXor = (b_row & 7) << 4;
  const uint32_t aOff = a_row * 128;
  const uint32_t bOff = b_row * 128;

  for (int c=0; c<NC; c++){
    const int st = c % NSTAGE;
    const uint32_t mbar = mb0 + st*8;
    mbar_wait(mbar, ph[st]); ph[st] ^= 1;
    if (c + NSTAGE < NC && tid == 0) expect_tx(mbar, TX);

    const uint32_t base = sbase + st*STRIDE;
    #pragma unroll
    for (int sub=0; sub<4; sub++){
      const uint32_t aSub = base + sub*8192 + aOff;
      const uint32_t wSub = base + WOFF + sub*4096 + bOff;
      #pragma unroll
      for (int k16=0; k16<4; k16++){
        const uint32_t ak = (((uint32_t)(k16*32) + a_kb) ^ aXor);
        const uint32_t bk = (((uint32_t)(k16*32) + b_kb) ^ bXor);
        uint32_t A4[4];
        ldsm4(A4, aSub + ak);
        if (MODE == 3){
          uint32_t A8[4], B4[4], B6[4];
          ldsm4(A8, base + 32768 + sub*8192 + aOff + ak);
          ldsm4(B4, wSub + bk);
          ldsm4(B6, wSub + 16384 + bk);
          mma16816(C[0], A4, B4[0], B4[1]);
          mma16816(C[1], A4, B4[2], B4[3]);
          mma16816(C[2], A8, B6[0], B6[1]);
          mma16816(C[3], A8, B6[2], B6[3]);
        } else {
          #pragma unroll
          for (int w=0; w<NWB; w++){
            uint32_t B4[4];
            ldsm4(B4, wSub + w*16384 + bk);
            mma16816(C[2*w+0], A4, B4[0], B4[1]);
            mma16816(C[2*w+1], A4, B4[2], B4[3]);
          }
        }
      }
    }
    __syncthreads();
    if (c + NSTAGE < NC) load_chunk(c+NSTAGE, st);
  }

  // epilogue
  #pragma unroll
  for (int f=0; f<2; f++){
    const int col = j0t*16 + wn*8 + f*4 + (lane & 3);
    #pragma unroll
    for (int hf=0; hf<2; hf++){
      const int m = m0 + wm*16 + (lane>>2) + hf*8;
      const int idx = m*NH + col;
      if (MODE == 0){
        float cv = C[f][hf*2], hv = C[f][hf*2+1];
        float sp = __ldcg(resid + idx);
        float g = 1.f/(1.f + __expf(-cv));
        float v = fmaf(g, act_fn(act, hv) - sp, sp);
        outS[idx] = v;
        if (swz) st_swz(swz, m, col, __float2half_rn(v));
      } else if (MODE == 1){
        float sp = __ldcg(resid + idx);
        #pragma unroll
        for (int w=0; w<3; w++){
          float g = 1.f/(1.f + __expf(-C[2*w+f][hf*2]));
          float v = fmaf(g, act_fn((w==2)?2:1, C[2*w+f][hf*2+1]) - sp, sp);
          g_s[2+w][idx] = v;
          if (w < 2) st_swz(&g_sw[2+w][0][0][0], m, col, __float2half_rn(v));
        }
      } else if (MODE == 3){
        float sp2 = __ldcg(resid + idx);
        float g4 = 1.f/(1.f + __expf(-C[f][hf*2]));
        float v5 = fmaf(g4, tanhf(C[f][hf*2+1]) - sp2, sp2);
        g_s[5][idx] = v5;
        st_swz(&g_sw[5][0][0][0], m, col, __float2half_rn(v5));
        float sp3 = __ldcg(resid2 + idx);
        float g6 = 1.f/(1.f + __expf(-C[2+f][hf*2]));
        float v7 = fmaf(g6, tanhf(C[2+f][hf*2+1]) - sp3, sp3);
        g_s[7][idx] = v7;
      } else {
        float s5v = __ldcg(resid + idx);
        float g5 = 1.f/(1.f + __expf(-C[f][hf*2]));
        float s6 = fmaf(g5, 1.f/(1.f + __expf(-C[f][hf*2+1])) - s5v, s5v);
        float g7 = 1.f/(1.f + __expf(-C[2+f][hf*2]));
        float s8 = fmaf(g7, fmaxf(C[2+f][hf*2+1], 0.f) - s5v, s5v);
        float mv = (__ldcg(&g_s[1][idx]) + __ldcg(&g_s[2][idx]) +
                    __ldcg(&g_s[3][idx]) + __ldcg(&g_s[4][idx]) +
                    s5v + s6 + __ldcg(&g_s[7][idx]) + s8) * 0.125f;
        g_hbuf[idx] = mv;
        st_swz(&g_sw[6][0][0][0], m, col, __float2half_rn(mv));
        out[((size_t)m*TT + t)*NH + col] = mv;
        if (t == TT-1) out[(size_t)BB*TT*NH + idx] = mv;
      }
    }
  }
}

// ---------------- persistent scan kernel (two independent half-domains) ----------------
__global__ void __launch_bounds__(NT,1) rnn_persistent(float* __restrict__ out){
  extern __shared__ __align__(128) unsigned char dsm[];
  __shared__ __align__(8) uint64_t s_mbar[4];

  const int tid = threadIdx.x;
  uint32_t sbase, mb0;
  { uint32_t a; asm("{ .reg .u64 t; cvta.to.shared.u64 t, %1; cvt.u32.u64 %0, t; }" : "=r"(a) : "l"(dsm)); sbase = a; }
  { uint32_t a; asm("{ .reg .u64 t; cvta.to.shared.u64 t, %1; cvt.u32.u64 %0, t; }" : "=r"(a) : "l"(&s_mbar[0])); mb0 = a; }

  if (tid == 0){
    #pragma unroll
    for (int b=0;b<4;b++)
      asm volatile("mbarrier.init.shared.b64 [%0], %1;" :: "r"(mb0+b*8), "r"(1u) : "memory");
  }
  __syncthreads();

  const unsigned grpSize = gridDim.x >> 1;
  const int grp = (blockIdx.x >= (int)grpSize) ? 1 : 0;
  const int lb  = blockIdx.x - grp*(int)grpSize;
  const int half = grp;
  const int m0 = half*64;

  int ph[4] = {0,0,0,0};
  unsigned target = 0;

  for (int t = 0; t < TT; t++){
    // G0: [x_t | h] @ W0 -> s0 (tanh, resid h). K=2048 (NC=8)
    for (int j0t = lb; j0t < 64; j0t += grpSize)
      job<0,true>(&g_xw[t][half][0][0], &g_sw[6][half][0][0],
                  g_w0w[j0t], nullptr, nullptr,
                  g_hbuf, nullptr, g_s[0], &g_sw[0][0][0][0],
                  m0, j0t, 3, 8, sbase, mb0, ph, tid, out, t);
    gsync(target, grp, grpSize);

    // G1: gene0 (sigmoid) s0 -> s1
    for (int j0t = lb; j0t < 64; j0t += grpSize)
      job<0,false>(&g_sw[0][half][0][0], nullptr,
                   g_wsw[0][j0t], nullptr, nullptr,
                   g_s[0], nullptr, g_s[1], &g_sw[1][0][0][0],
                   m0, j0t, 0, 4, sbase, mb0, ph, tid, out, t);
    gsync(target, grp, grpSize);

    // G2 fused: genes 1,2,3 from s1 -> s2,s3,s4
    for (int j0t = lb; j0t < 64; j0t += grpSize)
      job<1,false>(&g_sw[1][half][0][0], nullptr,
                   g_wsw[1][j0t], g_wsw[2][j0t], g_wsw[3][j0t],
                   g_s[1], nullptr, nullptr, nullptr,
                   m0, j0t, 0, 4, sbase, mb0, ph, tid, out, t);
    gsync(target, grp, grpSize);

    // G3 fused: gene4 (s2->s5) + gene6 (s3->s7), dual-A
    for (int j0t = lb; j0t < 64; j0t += grpSize)
      job<3,false>(&g_sw[2][half][0][0], &g_sw[3][half][0][0],
                   g_wsw[4][j0t], g_wsw[6][j0t], nullptr,
                   g_s[2], g_s[3], nullptr, nullptr,
                   m0, j0t, 3, 4, sbase, mb0, ph, tid, out, t);
    gsync(target, grp, grpSize);

    // G4+F fused: genes 5+7 from s5; finalize h
    for (int j0t = lb; j0t < 64; j0t += grpSize)
      job<2,false>(&g_sw[5][half][0][0], nullptr,
                   g_wsw[5][j0t], g_wsw[7][j0t], nullptr,
                   g_s[5], nullptr, nullptr, nullptr,
                   m0, j0t, 0, 4, sbase, mb0, ph, tid, out, t);
    gsync(target, grp, grpSize);
  }
}

// ---------------- prologue kernels ----------------
__global__ void wswz(const float* __restrict__ in, unsigned char* __restrict__ outp, int K){
  __shared__ float tile[32][65];
  const float* src = in + (size_t)blockIdx.z*K*2048;
  unsigned char* dst = outp + (((size_t)blockIdx.z*64 + blockIdx.x)*(K/64) + blockIdx.y)*4096;
  int j0 = blockIdx.x*16, k0 = blockIdx.y*64;
  int tx = threadIdx.x, ty = threadIdx.y;
  int w = tx;
  int col = (j0 + (w>>1)) + (w&1)*1024;
  for (int r=0;r<8;r++){
    int k = ty + r*8;
    tile[w][k] = src[(size_t)(k0+k)*2048 + col];
  }
  __syncthreads();
  for (int q=0;q<4;q++){
    int ww = ty + q*8;
    __half2 v = __floats2half2_rn(tile[ww][tx*2], tile[ww][tx*2+1]);
    uint32_t o = (uint32_t)(ww*128 + tx*4);
    o ^= (o>>3)&0x70;
    *(__half2*)(dst + o) = v;
  }
}

__global__ void xswz(const float* __restrict__ x, unsigned char* __restrict__ xs){
  int t = blockIdx.x;
  int half = blockIdx.y >> 4, st = blockIdx.y & 15;
  unsigned char* dst = xs + (((size_t)t*2 + half)*16 + st)*8192;
  int tid = threadIdx.x;
  int row = tid >> 2, kq = (tid & 3)*16;
  const float* src = x + ((size_t)(half*64 + row)*TT + t)*NI + st*64 + kq;
  #pragma unroll
  for (int i=0;i<2;i++){
    float4 a = *(const float4*)(src + i*8);
    float4 b = *(const float4*)(src + i*8 + 4);
    __half2 h0 = __floats2half2_rn(a.x,a.y), h1 = __floats2half2_rn(a.z,a.w);
    __half2 h2 = __floats2half2_rn(b.x,b.y), h3 = __floats2half2_rn(b.z,b.w);
    uint32_t o = (uint32_t)(row*128 + (kq + i*8)*2);
    o ^= (o>>3)&0x70;
    *(uint4*)(dst + o) = make_uint4(*(uint32_t*)&h0, *(uint32_t*)&h1,
                                    *(uint32_t*)&h2, *(uint32_t*)&h3);
  }
}

__global__ void hswz(const float* __restrict__ h0){
  int tid = blockIdx.x*blockDim.x + threadIdx.x;
  int m = tid >> 10, k = tid & 1023;
  float v = h0[tid];
  g_hbuf[tid] = v;
  st_swz(&g_sw[6][0][0][0], m, k, __float2half_rn(v));
}

__global__ void reset_kernel(){
  g_arr[0][0] = 0; g_arr[1][0] = 0; g_epo[0][0] = 0; g_epo[1][0] = 0;
}

// ---------------- host launch ----------------
extern "C" void kernel_launch(void* const* d_in, const int* in_sizes, int n_in,
                              void* d_out, int out_size){
  const float *x=nullptr, *h0=nullptr, *W0=nullptr, *Ws=nullptr;
  for (int i=0;i<n_in;i++){
    long n = in_sizes[i];
    if      (n == (long)BB*TT*NI)   x  = (const float*)d_in[i];
    else if (n == (long)BB*NH)      h0 = (const float*)d_in[i];
    else if (n == (long)2048*2048)  W0 = (const float*)d_in[i];
    else if (n == (long)8*NH*2048)  Ws = (const float*)d_in[i];
  }
  if (!x || !h0 || !W0 || !Ws) return;
  float* out = (float*)d_out;

  void* p;
  cudaGetSymbolAddress(&p, g_xw);  unsigned char* xw_p = (unsigned char*)p;
  cudaGetSymbolAddress(&p, g_w0w); unsigned char* w0_p = (unsigned char*)p;
  cudaGetSymbolAddress(&p, g_wsw); unsigned char* ws_p = (unsigned char*)p;

  cudaFuncSetAttribute(rnn_persistent, cudaFuncAttributeMaxDynamicSharedMemorySize, SMEM_DYN);

  int dev = 0, nsm = 0;
  cudaGetDevice(&dev);
  cudaDeviceGetAttribute(&nsm, cudaDevAttrMultiProcessorCount, dev);
  int grid = (nsm < GRID) ? (nsm & ~1) : GRID;

  wswz<<<dim3(64,32,1), dim3(32,8)>>>(W0, w0_p, 2048);
  wswz<<<dim3(64,16,8), dim3(32,8)>>>(Ws, ws_p, 1024);
  xswz<<<dim3(TT,32), 256>>>(x, xw_p);
  hswz<<<512,256>>>(h0);
  reset_kernel<<<1,1>>>();

  rnn_persistent<<<grid, NT, SMEM_DYN>>>(out);
  (void)out_size;
}